// round 10
// baseline (speedup 1.0000x reference)
#include <cuda_runtime.h>
#include <math.h>
#include <stdint.h>

#define NN 1000
#define FF 64
#define BTOT 192          // B*T
#define EE 16000
#define EPAD 20000        // per-node padded-to-4 edge lists
#define NTERMS 9
#define KC (NTERMS*FF)    // 576
#define MROWS (BTOT*NN)   // 192000
#define LDIM 768000       // T*N*F
#define CC 10
#define BB 16
#define LN_EPS 1e-5f

// ---------------- static device scratch ----------------
__device__ float g_basis[(size_t)MROWS * KC];   // 442 MB: 9 Chebyshev terms, interleaved
__device__ float g_hn[(size_t)MROWS * FF];      // 49 MB: post-LN hidden
__device__ float g_Wcat[KC * 128];              // stacked weights (z|h), tf32-rounded
__device__ int   g_pptr_src[NN + 1], g_pptr_dst[NN + 1];  // padded CSR offsets (mult of 4)
__device__ __align__(16) unsigned short g_i16_dst[EPAD];  // by-dst, stores src (pad: idx 0, w 0)
__device__ __align__(16) unsigned short g_i16_src[EPAD];  // by-src, stores dst
__device__ __align__(16) float g_wq_dst[EPAD];            // 1/deg_out[src], pads 0
__device__ __align__(16) float g_wq_src[EPAD];            // 1.0, pads 0
__device__ float g_inv_in[NN];

__device__ __forceinline__ uint32_t f2tf32(float f) {
    uint32_t u;
    asm("cvt.rna.tf32.f32 %0, %1;" : "=r"(u) : "f"(f));
    return u;
}

__device__ __forceinline__ void mma_tf32(float c[4], const uint32_t a[4],
                                         uint32_t b0, uint32_t b1) {
    asm volatile(
        "mma.sync.aligned.m16n8k8.row.col.f32.tf32.tf32.f32 "
        "{%0,%1,%2,%3}, {%4,%5,%6,%7}, {%8,%9}, {%0,%1,%2,%3};"
        : "+f"(c[0]), "+f"(c[1]), "+f"(c[2]), "+f"(c[3])
        : "r"(a[0]), "r"(a[1]), "r"(a[2]), "r"(a[3]), "r"(b0), "r"(b1));
}

// ---------------- single-block CSR setup + weight stacking ----------------
__global__ void __launch_bounds__(1024) setup_kernel(const int* __restrict__ ei,
                                                     const float* __restrict__ Wz,
                                                     const float* __restrict__ Wh) {
    __shared__ int s_cnt_src[NN], s_cnt_dst[NN];
    __shared__ int s_ptr_src[NN + 1], s_ptr_dst[NN + 1];
    __shared__ int s_fill_src[NN], s_fill_dst[NN];
    int tid = threadIdx.x;

    // weight stacking (independent of CSR work)
    for (int t = tid; t < KC * 128; t += 1024) {
        int kk = t >> 7;            // [0,576)
        int j  = t & 127;
        int term = kk / FF;
        int ci   = kk % FF;
        const float* W = (j < FF) ? Wz : Wh;
        int co = (j < FF) ? j : j - FF;
        float v;
        if (term == 0) {
            v = W[((0 * 5 + 0) * 128 + ci) * 64 + co] + W[((1 * 5 + 0) * 128 + ci) * 64 + co];
        } else if (term <= 4) {
            v = W[((0 * 5 + term) * 128 + ci) * 64 + co];
        } else {
            v = W[((1 * 5 + (term - 4)) * 128 + ci) * 64 + co];
        }
        g_Wcat[kk * 128 + j] = __uint_as_float(f2tf32(v));
    }

    for (int i = tid; i < NN; i += 1024) {
        s_cnt_src[i] = 0; s_cnt_dst[i] = 0;
        s_fill_src[i] = 0; s_fill_dst[i] = 0;
    }
    __syncthreads();
    for (int e = tid; e < EE; e += 1024) {
        atomicAdd(&s_cnt_src[ei[e]], 1);
        atomicAdd(&s_cnt_dst[ei[EE + e]], 1);
    }
    __syncthreads();
    if (tid == 0) {
        int s = 0, t = 0;
        for (int n = 0; n < NN; n++) {
            s_ptr_src[n] = s; s += (s_cnt_src[n] + 3) & ~3;
            s_ptr_dst[n] = t; t += (s_cnt_dst[n] + 3) & ~3;
        }
        s_ptr_src[NN] = s; s_ptr_dst[NN] = t;
    }
    __syncthreads();
    for (int i = tid; i <= NN; i += 1024) {
        g_pptr_src[i] = s_ptr_src[i];
        g_pptr_dst[i] = s_ptr_dst[i];
    }
    for (int n = tid; n < NN; n += 1024)
        g_inv_in[n] = 1.0f / (float)s_cnt_dst[n];
    for (int i = tid; i < EPAD; i += 1024) {
        g_i16_dst[i] = 0; g_i16_src[i] = 0;
        g_wq_dst[i] = 0.f; g_wq_src[i] = 0.f;
    }
    __syncthreads();
    for (int e = tid; e < EE; e += 1024) {
        int s = ei[e], d = ei[EE + e];
        int p = atomicAdd(&s_fill_dst[d], 1);
        int slot = s_ptr_dst[d] + p;
        g_i16_dst[slot] = (unsigned short)s;
        g_wq_dst[slot] = 1.0f / (float)s_cnt_src[s];   // 1/deg_out[src]
        int q = atomicAdd(&s_fill_src[s], 1);
        int slot2 = s_ptr_src[s] + q;
        g_i16_src[slot2] = (unsigned short)d;
        g_wq_src[slot2] = 1.0f;
    }
}

// ---------------- vectorized gather propagation (both directions in one launch) ----------------
// tin < 0: gather directly from x (row stride 64 floats); dir-0 group also
// copies its x row into basis term 0 (replaces the old copy_t0 kernel).
__global__ void __launch_bounds__(128) prop_pair_kernel(
    const float* __restrict__ x,
    int tin_o, int tin_i, int tout_o, int tout_i, int tsub, float alpha)
{
    int tid = threadIdx.x;
    int g = tid >> 4, l = tid & 15;
    int flat = blockIdx.x * 8 + g;        // [0, MROWS)
    int bt = flat / NN, n = flat - bt * NN;
    int dir = blockIdx.y;

    const unsigned short* idx;
    const float* wq;
    int b0, b1, tin, tout;
    if (dir == 0) {
        idx = g_i16_dst; wq = g_wq_dst;
        b0 = g_pptr_dst[n]; b1 = g_pptr_dst[n + 1];
        tin = tin_o; tout = tout_o;
    } else {
        idx = g_i16_src; wq = g_wq_src;
        b0 = g_pptr_src[n]; b1 = g_pptr_src[n + 1];
        tin = tin_i; tout = tout_i;
    }

    size_t stride;
    const char* base;
    if (tin < 0) {
        stride = (size_t)FF * 4;
        base = (const char*)x + (size_t)bt * NN * FF * 4 + l * 16;
    } else {
        stride = (size_t)KC * 4;
        base = (const char*)(g_basis + (size_t)bt * NN * KC + (size_t)tin * FF) + l * 16;
    }
    float4 acc = make_float4(0.f, 0.f, 0.f, 0.f);

    for (int e = b0; e < b1; e += 4) {
        uint2 q = *reinterpret_cast<const uint2*>(idx + e);
        float4 w = *reinterpret_cast<const float4*>(wq + e);
        int i0 = q.x & 0xffff, i1 = q.x >> 16;
        int i2 = q.y & 0xffff, i3 = q.y >> 16;
        float4 v0 = __ldg(reinterpret_cast<const float4*>(base + (size_t)i0 * stride));
        float4 v1 = __ldg(reinterpret_cast<const float4*>(base + (size_t)i1 * stride));
        float4 v2 = __ldg(reinterpret_cast<const float4*>(base + (size_t)i2 * stride));
        float4 v3 = __ldg(reinterpret_cast<const float4*>(base + (size_t)i3 * stride));
        acc.x += w.x * v0.x + w.y * v1.x + w.z * v2.x + w.w * v3.x;
        acc.y += w.x * v0.y + w.y * v1.y + w.z * v2.y + w.w * v3.y;
        acc.z += w.x * v0.z + w.y * v1.z + w.z * v2.z + w.w * v3.z;
        acc.w += w.x * v0.w + w.y * v1.w + w.z * v2.w + w.w * v3.w;
    }

    float scale = dir ? alpha * g_inv_in[n] : alpha;
    float4 r = make_float4(scale * acc.x, scale * acc.y, scale * acc.z, scale * acc.w);
    float* orow = g_basis + (size_t)flat * KC;
    if (tsub >= 0) {
        float4 s4 = *reinterpret_cast<const float4*>(orow + tsub * FF + l * 4);
        r.x -= s4.x; r.y -= s4.y; r.z -= s4.z; r.w -= s4.w;
    }
    if (tin < 0 && dir == 0) {  // write-through term 0 = X
        float4 xv = __ldg(reinterpret_cast<const float4*>(
            (const char*)x + ((size_t)flat * FF) * 4 + l * 16));
        *reinterpret_cast<float4*>(orow + l * 4) = xv;
    }
    *reinterpret_cast<float4*>(orow + tout * FF + l * 4) = r;
}

// ---------------- tf32 tensor-core GEMM (192000x576 @ 576x128) + gate + LN ----------------
// Pair-packed smem fragments: A stored as (k,k+4) uint2 pairs (stride 12 -> phase
// banks 12g+tg distinct mod 16), B as (r,r+4) uint2 pairs (stride 132 -> 4tg+g
// distinct mod 16). Fragment reads are LDS.64: 32 B-loads + 4 A-loads per tile
// per warp (was 64+8 scalar). Double-buffered, ONE sync per tile.
#define TM 128
#define TKC 16
#define AS2 12     // A row stride in uint2
#define BS2 132    // B row stride in uint2
__global__ void __launch_bounds__(256, 2) gemm_tc_kernel(
    const float* __restrict__ bz, const float* __restrict__ bh,
    const float* __restrict__ lng, const float* __restrict__ lnb)
{
    __shared__ uint2 As[2][TM * AS2];
    __shared__ uint2 Bs[2][8 * BS2];

    int tid = threadIdx.x;
    int w = tid >> 5, lane = tid & 31;
    int g = lane >> 2, tg = lane & 3;
    int block_row = blockIdx.x * TM;

    float acc[16][4];
#pragma unroll
    for (int j = 0; j < 16; j++)
#pragma unroll
        for (int i = 0; i < 4; i++) acc[j][i] = 0.f;

    // A loaders: all 256 threads, 2 per row, 8 consecutive k each
    int arow = tid >> 1, kha = tid & 1;
    const float* aptr = &g_basis[(size_t)(block_row + arow) * KC + kha * 8];
    // B loaders: threads 0..127: q = pair-row (0..7), 8 consecutive cols
    int q = (tid & 127) >> 4;
    int colo = (tid & 15) * 8;
    int r1 = (q >> 2) * 8 + (q & 3);          // k-within-tile of pair slot 0
    const float* bptr = &g_Wcat[r1 * 128 + colo];
    bool bload = tid < 128;

    // prologue prefetch (tile 0)
    float4 a0 = *reinterpret_cast<const float4*>(aptr);
    float4 a1 = *reinterpret_cast<const float4*>(aptr + 4);
    float4 b00, b01, b10, b11;
    if (bload) {
        b00 = *reinterpret_cast<const float4*>(bptr);
        b01 = *reinterpret_cast<const float4*>(bptr + 4);
        b10 = *reinterpret_cast<const float4*>(bptr + 512);   // row r1+4
        b11 = *reinterpret_cast<const float4*>(bptr + 516);
    }

    const int NT = KC / TKC;   // 36 tiles
#pragma unroll 1
    for (int t = 0; t < NT; t++) {
        int buf = t & 1;
        // A: pairs (k, k+4) -> uint4 stores
        uint4* adst = reinterpret_cast<uint4*>(&As[buf][arow * AS2 + kha * 4]);
        adst[0] = make_uint4(f2tf32(a0.x), f2tf32(a1.x), f2tf32(a0.y), f2tf32(a1.y));
        adst[1] = make_uint4(f2tf32(a0.z), f2tf32(a1.z), f2tf32(a0.w), f2tf32(a1.w));
        if (bload) {
            uint4* bdst = reinterpret_cast<uint4*>(&Bs[buf][q * BS2 + colo]);
            bdst[0] = make_uint4(__float_as_uint(b00.x), __float_as_uint(b10.x),
                                 __float_as_uint(b00.y), __float_as_uint(b10.y));
            bdst[1] = make_uint4(__float_as_uint(b00.z), __float_as_uint(b10.z),
                                 __float_as_uint(b00.w), __float_as_uint(b10.w));
            bdst[2] = make_uint4(__float_as_uint(b01.x), __float_as_uint(b11.x),
                                 __float_as_uint(b01.y), __float_as_uint(b11.y));
            bdst[3] = make_uint4(__float_as_uint(b01.z), __float_as_uint(b11.z),
                                 __float_as_uint(b01.w), __float_as_uint(b11.w));
        }
        __syncthreads();

        if (t + 1 < NT) {   // prefetch next tile while MMAs run
            int k1 = (t + 1) * TKC;
            a0 = *reinterpret_cast<const float4*>(aptr + k1);
            a1 = *reinterpret_cast<const float4*>(aptr + k1 + 4);
            if (bload) {
                b00 = *reinterpret_cast<const float4*>(bptr + k1 * 128);
                b01 = *reinterpret_cast<const float4*>(bptr + k1 * 128 + 4);
                b10 = *reinterpret_cast<const float4*>(bptr + k1 * 128 + 512);
                b11 = *reinterpret_cast<const float4*>(bptr + k1 * 128 + 516);
            }
        }

        const uint2* Ab = &As[buf][0];
        const uint2* Bb = &Bs[buf][0];
#pragma unroll
        for (int kh = 0; kh < 2; kh++) {
            uint2 pa0 = Ab[(w * 16 + g) * AS2 + kh * 4 + tg];      // (a0, a2)
            uint2 pa1 = Ab[(w * 16 + g + 8) * AS2 + kh * 4 + tg];  // (a1, a3)
            uint32_t a[4] = {pa0.x, pa1.x, pa0.y, pa1.y};
#pragma unroll
            for (int j = 0; j < 16; j++) {
                uint2 pb = Bb[(kh * 4 + tg) * BS2 + j * 8 + g];    // (b_r, b_r+4)
                mma_tf32(acc[j], a, pb.x, pb.y);
            }
        }
        // single sync per tile: next iteration's pre-compute sync protects buffers
    }

    // ---- epilogue: gate + LayerNorm, register-resident ----
#pragma unroll
    for (int rs = 0; rs < 2; rs++) {
        int row = block_row + w * 16 + g + rs * 8;
        float gv[8][2];
        float sum = 0.f, sq = 0.f;
#pragma unroll
        for (int j = 0; j < 8; j++) {
#pragma unroll
            for (int s = 0; s < 2; s++) {
                int col = j * 8 + tg * 2 + s;
                float vz = acc[j][rs * 2 + s] + __ldg(bz + col);
                float vh = acc[j + 8][rs * 2 + s] + __ldg(bh + col);
                float z = 1.f / (1.f + expf(-vz));
                float val = fmaxf(0.f, (1.f - z) * tanhf(vh));
                gv[j][s] = val;
                sum += val; sq += val * val;
            }
        }
        sum += __shfl_xor_sync(0xffffffffu, sum, 1);
        sq  += __shfl_xor_sync(0xffffffffu, sq, 1);
        sum += __shfl_xor_sync(0xffffffffu, sum, 2);
        sq  += __shfl_xor_sync(0xffffffffu, sq, 2);
        float mu = sum * (1.f / 64.f);
        float var = fmaxf(sq * (1.f / 64.f) - mu * mu, 0.f);
        float rstd = rsqrtf(var + LN_EPS);
        float* orow = g_hn + (size_t)row * FF;
#pragma unroll
        for (int j = 0; j < 8; j++) {
            int col = j * 8 + tg * 2;
            float2 o;
            o.x = (gv[j][0] - mu) * rstd * __ldg(lng + col)     + __ldg(lnb + col);
            o.y = (gv[j][1] - mu) * rstd * __ldg(lng + col + 1) + __ldg(lnb + col + 1);
            *reinterpret_cast<float2*>(orow + col) = o;
        }
    }
}

// ---------------- final linear head ----------------
__global__ void out_init_kernel(float* __restrict__ out, const float* __restrict__ lb) {
    int i = threadIdx.x;
    if (i < BB * CC) out[i] = lb[i % CC];
}

#define CH 1024
__global__ void __launch_bounds__(256) final_linear_kernel(
    const float* __restrict__ lin_w, float* __restrict__ out)
{
    __shared__ float ws[CC][CH];
    __shared__ float red[8][CC];
    int base = blockIdx.x * CH;   // 750 blocks * 1024 = 768000
    int tid = threadIdx.x;
    for (int i = tid; i < CC * CH; i += 256) {
        int c = i / CH, o = i % CH;
        ws[c][o] = lin_w[(size_t)c * LDIM + base + o];
    }
    __syncthreads();
    int w = tid >> 5, lane = tid & 31;
    for (int b = 0; b < BB; b++) {
        float a[CC];
#pragma unroll
        for (int c = 0; c < CC; c++) a[c] = 0.f;
        const float* hb = g_hn + (size_t)b * LDIM + base;
        for (int i = tid; i < CH; i += 256) {
            float hv = hb[i];
#pragma unroll
            for (int c = 0; c < CC; c++) a[c] += hv * ws[c][i];
        }
#pragma unroll
        for (int o = 16; o; o >>= 1)
#pragma unroll
            for (int c = 0; c < CC; c++) a[c] += __shfl_down_sync(0xffffffffu, a[c], o);
        if (lane == 0)
#pragma unroll
            for (int c = 0; c < CC; c++) red[w][c] = a[c];
        __syncthreads();
        if (tid < CC) {
            float s = 0.f;
#pragma unroll
            for (int ww = 0; ww < 8; ww++) s += red[ww][tid];
            atomicAdd(&out[b * CC + tid], s);
        }
        __syncthreads();
    }
}

// ---------------- launch ----------------
extern "C" void kernel_launch(void* const* d_in, const int* in_sizes, int n_in,
                              void* d_out, int out_size) {
    const float* x    = (const float*)d_in[0];
    const int*   ei   = (const int*)d_in[1];
    const float* Wz   = (const float*)d_in[2];
    const float* bz   = (const float*)d_in[3];
    // d_in[4], d_in[5] = W_r, b_r -> dead code (h0 == 0)
    const float* Wh   = (const float*)d_in[6];
    const float* bh   = (const float*)d_in[7];
    const float* lng  = (const float*)d_in[8];
    const float* lnb  = (const float*)d_in[9];
    const float* linw = (const float*)d_in[10];
    const float* linb = (const float*)d_in[11];
    float* out = (float*)d_out;

    setup_kernel<<<1, 1024>>>(ei, Wz, Wh);                           // launch 1

    dim3 pgrid(MROWS / 8, 2);
    // terms: 0=X, 1..4 = out-chain, 5..8 = in-chain (shared Tx0 history = out-chain terms)
    prop_pair_kernel<<<pgrid, 128>>>(x, -1, -1, 1, 5, -1, 1.0f);     // launch 2 (+ term0 copy)
    prop_pair_kernel<<<pgrid, 128>>>(x, 1, 5, 2, 6, 0, 2.0f);        // launch 3
    prop_pair_kernel<<<pgrid, 128>>>(x, 2, 6, 3, 7, 1, 2.0f);        // launch 4
    prop_pair_kernel<<<pgrid, 128>>>(x, 3, 7, 4, 8, 2, 2.0f);        // launch 5

    gemm_tc_kernel<<<MROWS / TM, 256>>>(bz, bh, lng, lnb);           // launch 6 (profiled slot)

    out_init_kernel<<<1, 256>>>(out, linb);
    final_linear_kernel<<<LDIM / CH, 256>>>(linw, out);
}

// round 11
// speedup vs baseline: 1.0238x; 1.0238x over previous
#include <cuda_runtime.h>
#include <math.h>
#include <stdint.h>

#define NN 1000
#define FF 64
#define BTOT 192          // B*T
#define EE 16000
#define EPAD 20000        // per-node padded-to-4 edge lists
#define NTERMS 9
#define KC (NTERMS*FF)    // 576
#define MROWS (BTOT*NN)   // 192000
#define LDIM 768000       // T*N*F
#define CC 10
#define BB 16
#define LN_EPS 1e-5f

// ---------------- static device scratch ----------------
__device__ float g_basis[(size_t)MROWS * KC];   // 442 MB: 9 Chebyshev terms, interleaved
__device__ float g_hn[(size_t)MROWS * FF];      // 49 MB: post-LN hidden
__device__ float g_Wcat[KC * 128];              // stacked weights (z|h), tf32-rounded
__device__ int   g_pptr_src[NN + 1], g_pptr_dst[NN + 1];  // padded CSR offsets (mult of 4)
__device__ __align__(16) unsigned short g_i16_dst[EPAD];  // by-dst, stores src (pad: idx 0, w 0)
__device__ __align__(16) unsigned short g_i16_src[EPAD];  // by-src, stores dst
__device__ __align__(16) float g_wq_dst[EPAD];            // 1/deg_out[src], pads 0
__device__ __align__(16) float g_wq_src[EPAD];            // 1.0, pads 0
__device__ float g_inv_in[NN];

__device__ __forceinline__ uint32_t f2tf32(float f) {
    uint32_t u;
    asm("cvt.rna.tf32.f32 %0, %1;" : "=r"(u) : "f"(f));
    return u;
}

__device__ __forceinline__ void mma_tf32(float c[4], const uint32_t a[4],
                                         uint32_t b0, uint32_t b1) {
    asm volatile(
        "mma.sync.aligned.m16n8k8.row.col.f32.tf32.tf32.f32 "
        "{%0,%1,%2,%3}, {%4,%5,%6,%7}, {%8,%9}, {%0,%1,%2,%3};"
        : "+f"(c[0]), "+f"(c[1]), "+f"(c[2]), "+f"(c[3])
        : "r"(a[0]), "r"(a[1]), "r"(a[2]), "r"(a[3]), "r"(b0), "r"(b1));
}

// ---------------- single-block CSR setup + weight stacking ----------------
__global__ void __launch_bounds__(1024) setup_kernel(const int* __restrict__ ei,
                                                     const float* __restrict__ Wz,
                                                     const float* __restrict__ Wh) {
    __shared__ int s_cnt_src[NN], s_cnt_dst[NN];
    __shared__ int s_ptr_src[NN + 1], s_ptr_dst[NN + 1];
    __shared__ int s_fill_src[NN], s_fill_dst[NN];
    int tid = threadIdx.x;

    // weight stacking (independent of CSR work)
    for (int t = tid; t < KC * 128; t += 1024) {
        int kk = t >> 7;            // [0,576)
        int j  = t & 127;
        int term = kk / FF;
        int ci   = kk % FF;
        const float* W = (j < FF) ? Wz : Wh;
        int co = (j < FF) ? j : j - FF;
        float v;
        if (term == 0) {
            v = W[((0 * 5 + 0) * 128 + ci) * 64 + co] + W[((1 * 5 + 0) * 128 + ci) * 64 + co];
        } else if (term <= 4) {
            v = W[((0 * 5 + term) * 128 + ci) * 64 + co];
        } else {
            v = W[((1 * 5 + (term - 4)) * 128 + ci) * 64 + co];
        }
        g_Wcat[kk * 128 + j] = __uint_as_float(f2tf32(v));
    }

    for (int i = tid; i < NN; i += 1024) {
        s_cnt_src[i] = 0; s_cnt_dst[i] = 0;
        s_fill_src[i] = 0; s_fill_dst[i] = 0;
    }
    __syncthreads();
    for (int e = tid; e < EE; e += 1024) {
        atomicAdd(&s_cnt_src[ei[e]], 1);
        atomicAdd(&s_cnt_dst[ei[EE + e]], 1);
    }
    __syncthreads();
    if (tid == 0) {
        int s = 0, t = 0;
        for (int n = 0; n < NN; n++) {
            s_ptr_src[n] = s; s += (s_cnt_src[n] + 3) & ~3;
            s_ptr_dst[n] = t; t += (s_cnt_dst[n] + 3) & ~3;
        }
        s_ptr_src[NN] = s; s_ptr_dst[NN] = t;
    }
    __syncthreads();
    for (int i = tid; i <= NN; i += 1024) {
        g_pptr_src[i] = s_ptr_src[i];
        g_pptr_dst[i] = s_ptr_dst[i];
    }
    for (int n = tid; n < NN; n += 1024)
        g_inv_in[n] = 1.0f / (float)s_cnt_dst[n];
    for (int i = tid; i < EPAD; i += 1024) {
        g_i16_dst[i] = 0; g_i16_src[i] = 0;
        g_wq_dst[i] = 0.f; g_wq_src[i] = 0.f;
    }
    __syncthreads();
    for (int e = tid; e < EE; e += 1024) {
        int s = ei[e], d = ei[EE + e];
        int p = atomicAdd(&s_fill_dst[d], 1);
        int slot = s_ptr_dst[d] + p;
        g_i16_dst[slot] = (unsigned short)s;
        g_wq_dst[slot] = 1.0f / (float)s_cnt_src[s];   // 1/deg_out[src]
        int q = atomicAdd(&s_fill_src[s], 1);
        int slot2 = s_ptr_src[s] + q;
        g_i16_src[slot2] = (unsigned short)d;
        g_wq_src[slot2] = 1.0f;
    }
}

// ---------------- first diffusion step: gather from x, write terms 0/1/5 ----------------
// Specialized: constant row stride FF. dir0 group also writes term0 = x row.
__global__ void __launch_bounds__(128) prop_first_kernel(const float* __restrict__ x) {
    int tid = threadIdx.x;
    int g = tid >> 4, l = tid & 15;
    int flat = blockIdx.x * 8 + g;        // [0, MROWS)
    int bt = flat / NN, n = flat - bt * NN;
    int dir = blockIdx.y;

    const unsigned short* idx;
    const float* wq;
    int b0, b1, tout;
    if (dir == 0) {
        idx = g_i16_dst; wq = g_wq_dst;
        b0 = g_pptr_dst[n]; b1 = g_pptr_dst[n + 1];
        tout = 1;
    } else {
        idx = g_i16_src; wq = g_wq_src;
        b0 = g_pptr_src[n]; b1 = g_pptr_src[n + 1];
        tout = 5;
    }

    const float* base = x + (size_t)bt * NN * FF + l * 4;
    float4 acc = make_float4(0.f, 0.f, 0.f, 0.f);

    for (int e = b0; e < b1; e += 4) {
        uint2 q = *reinterpret_cast<const uint2*>(idx + e);
        float4 w = *reinterpret_cast<const float4*>(wq + e);
        int i0 = q.x & 0xffff, i1 = q.x >> 16;
        int i2 = q.y & 0xffff, i3 = q.y >> 16;
        float4 v0 = __ldg(reinterpret_cast<const float4*>(base + i0 * FF));
        float4 v1 = __ldg(reinterpret_cast<const float4*>(base + i1 * FF));
        float4 v2 = __ldg(reinterpret_cast<const float4*>(base + i2 * FF));
        float4 v3 = __ldg(reinterpret_cast<const float4*>(base + i3 * FF));
        acc.x += w.x * v0.x + w.y * v1.x + w.z * v2.x + w.w * v3.x;
        acc.y += w.x * v0.y + w.y * v1.y + w.z * v2.y + w.w * v3.y;
        acc.z += w.x * v0.z + w.y * v1.z + w.z * v2.z + w.w * v3.z;
        acc.w += w.x * v0.w + w.y * v1.w + w.z * v2.w + w.w * v3.w;
    }

    float scale = dir ? g_inv_in[n] : 1.0f;
    float4 r = make_float4(scale * acc.x, scale * acc.y, scale * acc.z, scale * acc.w);
    float* orow = g_basis + (size_t)flat * KC;
    if (dir == 0) {  // write-through term 0 = X
        float4 xv = __ldg(reinterpret_cast<const float4*>(x + (size_t)flat * FF + l * 4));
        *reinterpret_cast<float4*>(orow + l * 4) = xv;
    }
    *reinterpret_cast<float4*>(orow + tout * FF + l * 4) = r;
}

// ---------------- lean gather propagation (steps 2..4; R5-proven 32-reg version) ----------------
__global__ void __launch_bounds__(128) prop_pair_kernel(
    int tin_o, int tin_i, int tout_o, int tout_i, int tsub, float alpha)
{
    int tid = threadIdx.x;
    int g = tid >> 4, l = tid & 15;
    int flat = blockIdx.x * 8 + g;        // [0, MROWS)
    int bt = flat / NN, n = flat - bt * NN;
    int dir = blockIdx.y;

    const unsigned short* idx;
    const float* wq;
    int b0, b1, tin, tout;
    if (dir == 0) {
        idx = g_i16_dst; wq = g_wq_dst;
        b0 = g_pptr_dst[n]; b1 = g_pptr_dst[n + 1];
        tin = tin_o; tout = tout_o;
    } else {
        idx = g_i16_src; wq = g_wq_src;
        b0 = g_pptr_src[n]; b1 = g_pptr_src[n + 1];
        tin = tin_i; tout = tout_i;
    }

    const char* base = (const char*)(g_basis + (size_t)bt * NN * KC + tin * FF) + l * 16;
    float4 acc = make_float4(0.f, 0.f, 0.f, 0.f);

    for (int e = b0; e < b1; e += 4) {
        uint2 q = *reinterpret_cast<const uint2*>(idx + e);
        float4 w = *reinterpret_cast<const float4*>(wq + e);
        int i0 = q.x & 0xffff, i1 = q.x >> 16;
        int i2 = q.y & 0xffff, i3 = q.y >> 16;
        float4 v0 = __ldg(reinterpret_cast<const float4*>(base + (size_t)i0 * (KC * 4)));
        float4 v1 = __ldg(reinterpret_cast<const float4*>(base + (size_t)i1 * (KC * 4)));
        float4 v2 = __ldg(reinterpret_cast<const float4*>(base + (size_t)i2 * (KC * 4)));
        float4 v3 = __ldg(reinterpret_cast<const float4*>(base + (size_t)i3 * (KC * 4)));
        acc.x += w.x * v0.x + w.y * v1.x + w.z * v2.x + w.w * v3.x;
        acc.y += w.x * v0.y + w.y * v1.y + w.z * v2.y + w.w * v3.y;
        acc.z += w.x * v0.z + w.y * v1.z + w.z * v2.z + w.w * v3.z;
        acc.w += w.x * v0.w + w.y * v1.w + w.z * v2.w + w.w * v3.w;
    }

    float scale = dir ? alpha * g_inv_in[n] : alpha;
    float4 r = make_float4(scale * acc.x, scale * acc.y, scale * acc.z, scale * acc.w);
    float* orow = g_basis + (size_t)flat * KC;
    if (tsub >= 0) {
        float4 s4 = *reinterpret_cast<const float4*>(orow + tsub * FF + l * 4);
        r.x -= s4.x; r.y -= s4.y; r.z -= s4.z; r.w -= s4.w;
    }
    *reinterpret_cast<float4*>(orow + tout * FF + l * 4) = r;
}

// ---------------- tf32 tensor-core GEMM (192000x576 @ 576x128) + gate + LN ----------------
// Pair-packed smem fragments: A stored as (k,k+4) uint2 pairs (stride 12), B as
// (r,r+4) uint2 pairs (stride 132); conflict-free LDS.64 reads. Double-buffered,
// ONE sync per tile.
#define TM 128
#define TKC 16
#define AS2 12     // A row stride in uint2
#define BS2 132    // B row stride in uint2
__global__ void __launch_bounds__(256, 2) gemm_tc_kernel(
    const float* __restrict__ bz, const float* __restrict__ bh,
    const float* __restrict__ lng, const float* __restrict__ lnb)
{
    __shared__ uint2 As[2][TM * AS2];
    __shared__ uint2 Bs[2][8 * BS2];

    int tid = threadIdx.x;
    int w = tid >> 5, lane = tid & 31;
    int g = lane >> 2, tg = lane & 3;
    int block_row = blockIdx.x * TM;

    float acc[16][4];
#pragma unroll
    for (int j = 0; j < 16; j++)
#pragma unroll
        for (int i = 0; i < 4; i++) acc[j][i] = 0.f;

    // A loaders: all 256 threads, 2 per row, 8 consecutive k each
    int arow = tid >> 1, kha = tid & 1;
    const float* aptr = &g_basis[(size_t)(block_row + arow) * KC + kha * 8];
    // B loaders: threads 0..127: q = pair-row (0..7), 8 consecutive cols
    int q = (tid & 127) >> 4;
    int colo = (tid & 15) * 8;
    int r1 = (q >> 2) * 8 + (q & 3);          // k-within-tile of pair slot 0
    const float* bptr = &g_Wcat[r1 * 128 + colo];
    bool bload = tid < 128;

    // prologue prefetch (tile 0)
    float4 a0 = *reinterpret_cast<const float4*>(aptr);
    float4 a1 = *reinterpret_cast<const float4*>(aptr + 4);
    float4 b00, b01, b10, b11;
    if (bload) {
        b00 = *reinterpret_cast<const float4*>(bptr);
        b01 = *reinterpret_cast<const float4*>(bptr + 4);
        b10 = *reinterpret_cast<const float4*>(bptr + 512);   // row r1+4
        b11 = *reinterpret_cast<const float4*>(bptr + 516);
    }

    const int NT = KC / TKC;   // 36 tiles
#pragma unroll 1
    for (int t = 0; t < NT; t++) {
        int buf = t & 1;
        // A: pairs (k, k+4) -> uint4 stores
        uint4* adst = reinterpret_cast<uint4*>(&As[buf][arow * AS2 + kha * 4]);
        adst[0] = make_uint4(f2tf32(a0.x), f2tf32(a1.x), f2tf32(a0.y), f2tf32(a1.y));
        adst[1] = make_uint4(f2tf32(a0.z), f2tf32(a1.z), f2tf32(a0.w), f2tf32(a1.w));
        if (bload) {
            uint4* bdst = reinterpret_cast<uint4*>(&Bs[buf][q * BS2 + colo]);
            bdst[0] = make_uint4(__float_as_uint(b00.x), __float_as_uint(b10.x),
                                 __float_as_uint(b00.y), __float_as_uint(b10.y));
            bdst[1] = make_uint4(__float_as_uint(b00.z), __float_as_uint(b10.z),
                                 __float_as_uint(b00.w), __float_as_uint(b10.w));
            bdst[2] = make_uint4(__float_as_uint(b01.x), __float_as_uint(b11.x),
                                 __float_as_uint(b01.y), __float_as_uint(b11.y));
            bdst[3] = make_uint4(__float_as_uint(b01.z), __float_as_uint(b11.z),
                                 __float_as_uint(b01.w), __float_as_uint(b11.w));
        }
        __syncthreads();

        if (t + 1 < NT) {   // prefetch next tile while MMAs run
            int k1 = (t + 1) * TKC;
            a0 = *reinterpret_cast<const float4*>(aptr + k1);
            a1 = *reinterpret_cast<const float4*>(aptr + k1 + 4);
            if (bload) {
                b00 = *reinterpret_cast<const float4*>(bptr + k1 * 128);
                b01 = *reinterpret_cast<const float4*>(bptr + k1 * 128 + 4);
                b10 = *reinterpret_cast<const float4*>(bptr + k1 * 128 + 512);
                b11 = *reinterpret_cast<const float4*>(bptr + k1 * 128 + 516);
            }
        }

        const uint2* Ab = &As[buf][0];
        const uint2* Bb = &Bs[buf][0];
#pragma unroll
        for (int kh = 0; kh < 2; kh++) {
            uint2 pa0 = Ab[(w * 16 + g) * AS2 + kh * 4 + tg];      // (a0, a2)
            uint2 pa1 = Ab[(w * 16 + g + 8) * AS2 + kh * 4 + tg];  // (a1, a3)
            uint32_t a[4] = {pa0.x, pa1.x, pa0.y, pa1.y};
#pragma unroll
            for (int j = 0; j < 16; j++) {
                uint2 pb = Bb[(kh * 4 + tg) * BS2 + j * 8 + g];    // (b_r, b_r+4)
                mma_tf32(acc[j], a, pb.x, pb.y);
            }
        }
        // single sync per tile: next iteration's pre-compute sync protects buffers
    }

    // ---- epilogue: gate + LayerNorm, register-resident ----
#pragma unroll
    for (int rs = 0; rs < 2; rs++) {
        int row = block_row + w * 16 + g + rs * 8;
        float gv[8][2];
        float sum = 0.f, sq = 0.f;
#pragma unroll
        for (int j = 0; j < 8; j++) {
#pragma unroll
            for (int s = 0; s < 2; s++) {
                int col = j * 8 + tg * 2 + s;
                float vz = acc[j][rs * 2 + s] + __ldg(bz + col);
                float vh = acc[j + 8][rs * 2 + s] + __ldg(bh + col);
                float z = 1.f / (1.f + expf(-vz));
                float val = fmaxf(0.f, (1.f - z) * tanhf(vh));
                gv[j][s] = val;
                sum += val; sq += val * val;
            }
        }
        sum += __shfl_xor_sync(0xffffffffu, sum, 1);
        sq  += __shfl_xor_sync(0xffffffffu, sq, 1);
        sum += __shfl_xor_sync(0xffffffffu, sum, 2);
        sq  += __shfl_xor_sync(0xffffffffu, sq, 2);
        float mu = sum * (1.f / 64.f);
        float var = fmaxf(sq * (1.f / 64.f) - mu * mu, 0.f);
        float rstd = rsqrtf(var + LN_EPS);
        float* orow = g_hn + (size_t)row * FF;
#pragma unroll
        for (int j = 0; j < 8; j++) {
            int col = j * 8 + tg * 2;
            float2 o;
            o.x = (gv[j][0] - mu) * rstd * __ldg(lng + col)     + __ldg(lnb + col);
            o.y = (gv[j][1] - mu) * rstd * __ldg(lng + col + 1) + __ldg(lnb + col + 1);
            *reinterpret_cast<float2*>(orow + col) = o;
        }
    }
}

// ---------------- final linear head ----------------
__global__ void out_init_kernel(float* __restrict__ out, const float* __restrict__ lb) {
    int i = threadIdx.x;
    if (i < BB * CC) out[i] = lb[i % CC];
}

#define CH 1024
__global__ void __launch_bounds__(256) final_linear_kernel(
    const float* __restrict__ lin_w, float* __restrict__ out)
{
    __shared__ float ws[CC][CH];
    __shared__ float red[8][CC];
    int base = blockIdx.x * CH;   // 750 blocks * 1024 = 768000
    int tid = threadIdx.x;
    for (int i = tid; i < CC * CH; i += 256) {
        int c = i / CH, o = i % CH;
        ws[c][o] = lin_w[(size_t)c * LDIM + base + o];
    }
    __syncthreads();
    int w = tid >> 5, lane = tid & 31;
    for (int b = 0; b < BB; b++) {
        float a[CC];
#pragma unroll
        for (int c = 0; c < CC; c++) a[c] = 0.f;
        const float* hb = g_hn + (size_t)b * LDIM + base;
        for (int i = tid; i < CH; i += 256) {
            float hv = hb[i];
#pragma unroll
            for (int c = 0; c < CC; c++) a[c] += hv * ws[c][i];
        }
#pragma unroll
        for (int o = 16; o; o >>= 1)
#pragma unroll
            for (int c = 0; c < CC; c++) a[c] += __shfl_down_sync(0xffffffffu, a[c], o);
        if (lane == 0)
#pragma unroll
            for (int c = 0; c < CC; c++) red[w][c] = a[c];
        __syncthreads();
        if (tid < CC) {
            float s = 0.f;
#pragma unroll
            for (int ww = 0; ww < 8; ww++) s += red[ww][tid];
            atomicAdd(&out[b * CC + tid], s);
        }
        __syncthreads();
    }
}

// ---------------- launch ----------------
extern "C" void kernel_launch(void* const* d_in, const int* in_sizes, int n_in,
                              void* d_out, int out_size) {
    const float* x    = (const float*)d_in[0];
    const int*   ei   = (const int*)d_in[1];
    const float* Wz   = (const float*)d_in[2];
    const float* bz   = (const float*)d_in[3];
    // d_in[4], d_in[5] = W_r, b_r -> dead code (h0 == 0)
    const float* Wh   = (const float*)d_in[6];
    const float* bh   = (const float*)d_in[7];
    const float* lng  = (const float*)d_in[8];
    const float* lnb  = (const float*)d_in[9];
    const float* linw = (const float*)d_in[10];
    const float* linb = (const float*)d_in[11];
    float* out = (float*)d_out;

    setup_kernel<<<1, 1024>>>(ei, Wz, Wh);                           // launch 1

    dim3 pgrid(MROWS / 8, 2);
    // terms: 0=X, 1..4 = out-chain, 5..8 = in-chain (shared Tx0 history = out-chain terms)
    prop_first_kernel<<<pgrid, 128>>>(x);                            // launch 2 (terms 0,1,5)
    prop_pair_kernel<<<pgrid, 128>>>(1, 5, 2, 6, 0, 2.0f);           // launch 3
    prop_pair_kernel<<<pgrid, 128>>>(2, 6, 3, 7, 1, 2.0f);           // launch 4
    prop_pair_kernel<<<pgrid, 128>>>(3, 7, 4, 8, 2, 2.0f);           // launch 5

    gemm_tc_kernel<<<MROWS / TM, 256>>>(bz, bh, lng, lnb);           // launch 6

    out_init_kernel<<<1, 256>>>(out, linb);
    final_linear_kernel<<<LDIM / CH, 256>>>(linw, out);
}

// round 17
// speedup vs baseline: 1.0589x; 1.0343x over previous
#include <cuda_runtime.h>
#include <cuda_fp16.h>
#include <math.h>
#include <stdint.h>

#define NN 1000
#define FF 64
#define BTOT 192          // B*T
#define EE 16000
#define EPAD 20000        // per-node padded-to-4 edge lists
#define NTERMS 9
#define KC (NTERMS*FF)    // 576
#define MROWS (BTOT*NN)   // 192000
#define LDIM 768000       // T*N*F
#define CC 10
#define BB 16
#define LN_EPS 1e-5f
#define NSTAGE 36         // K stages of 16

// ---------------- static device scratch ----------------
__device__ float g_basis[(size_t)MROWS * KC];   // 442 MB: 9 Chebyshev terms, interleaved
__device__ float g_hn[(size_t)MROWS * FF];      // 49 MB: post-LN hidden
__device__ float g_Wcat2[128 * KC];             // stacked weights TRANSPOSED [n][k], fp32
__device__ uint2 g_Bpre[NSTAGE * 128 * 4];      // B pre-packed fp16 smem-layout tiles
__device__ int   g_pptr_src[NN + 1], g_pptr_dst[NN + 1];  // padded CSR offsets (mult of 4)
__device__ __align__(16) unsigned short g_i16_dst[EPAD];  // by-dst, stores src (pad: idx 0, w 0)
__device__ __align__(16) unsigned short g_i16_src[EPAD];  // by-src, stores dst
__device__ __align__(16) float g_wq_dst[EPAD];            // 1/deg_out[src], pads 0
__device__ __align__(16) float g_wq_src[EPAD];            // 1.0, pads 0
__device__ float g_inv_in[NN];

__device__ __forceinline__ uint32_t pack2(float a, float b) {
    __half2 h = __floats2half2_rn(a, b);      // .x (low) = a
    return *reinterpret_cast<uint32_t*>(&h);
}

__device__ __forceinline__ void mma_f16(float c[4],
                                        uint32_t a0, uint32_t a1, uint32_t a2, uint32_t a3,
                                        uint32_t b0, uint32_t b1) {
    asm volatile(
        "mma.sync.aligned.m16n8k16.row.col.f32.f16.f16.f32 "
        "{%0,%1,%2,%3}, {%4,%5,%6,%7}, {%8,%9}, {%0,%1,%2,%3};"
        : "+f"(c[0]), "+f"(c[1]), "+f"(c[2]), "+f"(c[3])
        : "r"(a0), "r"(a1), "r"(a2), "r"(a3), "r"(b0), "r"(b1));
}

// ---------------- single-block CSR setup + weight stacking + B pre-pack ----------------
__global__ void __launch_bounds__(1024) setup_kernel(const int* __restrict__ ei,
                                                     const float* __restrict__ Wz,
                                                     const float* __restrict__ Wh) {
    __shared__ int s_cnt_src[NN], s_cnt_dst[NN];
    __shared__ int s_ptr_src[NN + 1], s_ptr_dst[NN + 1];
    __shared__ int s_fill_src[NN], s_fill_dst[NN];
    int tid = threadIdx.x;

    // weight stacking TRANSPOSED: g_Wcat2[j][kk] (j = output col 0..127, kk = 0..575)
    for (int t = tid; t < KC * 128; t += 1024) {
        int kk = t >> 7;            // [0,576)
        int j  = t & 127;
        int term = kk / FF;
        int ci   = kk % FF;
        const float* W = (j < FF) ? Wz : Wh;
        int co = (j < FF) ? j : j - FF;
        float v;
        if (term == 0) {
            v = W[((0 * 5 + 0) * 128 + ci) * 64 + co] + W[((1 * 5 + 0) * 128 + ci) * 64 + co];
        } else if (term <= 4) {
            v = W[((0 * 5 + term) * 128 + ci) * 64 + co];
        } else {
            v = W[((1 * 5 + (term - 4)) * 128 + ci) * 64 + co];
        }
        g_Wcat2[(size_t)j * KC + kk] = v;
    }
    __syncthreads();
    // pre-pack B into fp16 smem-tile layout: g_Bpre[(ch*128+n)*4+p] =
    //   { h2(W[n][k0+2p], W[n][k0+2p+1]), h2(W[n][k0+2p+8], W[n][k0+2p+9]) }
    for (int t = tid; t < NSTAGE * 128 * 4; t += 1024) {
        int p  = t & 3;
        int n  = (t >> 2) & 127;
        int ch = t >> 9;
        const float* wr = &g_Wcat2[(size_t)n * KC + ch * 16];
        g_Bpre[t] = make_uint2(pack2(wr[2 * p], wr[2 * p + 1]),
                               pack2(wr[2 * p + 8], wr[2 * p + 9]));
    }

    for (int i = tid; i < NN; i += 1024) {
        s_cnt_src[i] = 0; s_cnt_dst[i] = 0;
        s_fill_src[i] = 0; s_fill_dst[i] = 0;
    }
    __syncthreads();
    for (int e = tid; e < EE; e += 1024) {
        atomicAdd(&s_cnt_src[ei[e]], 1);
        atomicAdd(&s_cnt_dst[ei[EE + e]], 1);
    }
    __syncthreads();
    if (tid == 0) {
        int s = 0, t = 0;
        for (int n = 0; n < NN; n++) {
            s_ptr_src[n] = s; s += (s_cnt_src[n] + 3) & ~3;
            s_ptr_dst[n] = t; t += (s_cnt_dst[n] + 3) & ~3;
        }
        s_ptr_src[NN] = s; s_ptr_dst[NN] = t;
    }
    __syncthreads();
    for (int i = tid; i <= NN; i += 1024) {
        g_pptr_src[i] = s_ptr_src[i];
        g_pptr_dst[i] = s_ptr_dst[i];
    }
    for (int n = tid; n < NN; n += 1024)
        g_inv_in[n] = 1.0f / (float)s_cnt_dst[n];
    for (int i = tid; i < EPAD; i += 1024) {
        g_i16_dst[i] = 0; g_i16_src[i] = 0;
        g_wq_dst[i] = 0.f; g_wq_src[i] = 0.f;
    }
    __syncthreads();
    for (int e = tid; e < EE; e += 1024) {
        int s = ei[e], d = ei[EE + e];
        int p = atomicAdd(&s_fill_dst[d], 1);
        int slot = s_ptr_dst[d] + p;
        g_i16_dst[slot] = (unsigned short)s;
        g_wq_dst[slot] = 1.0f / (float)s_cnt_src[s];   // 1/deg_out[src]
        int q = atomicAdd(&s_fill_src[s], 1);
        int slot2 = s_ptr_src[s] + q;
        g_i16_src[slot2] = (unsigned short)d;
        g_wq_src[slot2] = 1.0f;
    }
}

// ---------------- first diffusion step: gather from x, write terms 0/1/5 ----------------
__global__ void __launch_bounds__(128) prop_first_kernel(const float* __restrict__ x) {
    int tid = threadIdx.x;
    int g = tid >> 4, l = tid & 15;
    int flat = blockIdx.x * 8 + g;        // [0, MROWS)
    int bt = flat / NN, n = flat - bt * NN;
    int dir = blockIdx.y;

    const unsigned short* idx;
    const float* wq;
    int b0, b1, tout;
    if (dir == 0) {
        idx = g_i16_dst; wq = g_wq_dst;
        b0 = g_pptr_dst[n]; b1 = g_pptr_dst[n + 1];
        tout = 1;
    } else {
        idx = g_i16_src; wq = g_wq_src;
        b0 = g_pptr_src[n]; b1 = g_pptr_src[n + 1];
        tout = 5;
    }

    const float* base = x + (size_t)bt * NN * FF + l * 4;
    float4 acc = make_float4(0.f, 0.f, 0.f, 0.f);

    for (int e = b0; e < b1; e += 4) {
        uint2 q = *reinterpret_cast<const uint2*>(idx + e);
        float4 w = *reinterpret_cast<const float4*>(wq + e);
        int i0 = q.x & 0xffff, i1 = q.x >> 16;
        int i2 = q.y & 0xffff, i3 = q.y >> 16;
        float4 v0 = __ldg(reinterpret_cast<const float4*>(base + i0 * FF));
        float4 v1 = __ldg(reinterpret_cast<const float4*>(base + i1 * FF));
        float4 v2 = __ldg(reinterpret_cast<const float4*>(base + i2 * FF));
        float4 v3 = __ldg(reinterpret_cast<const float4*>(base + i3 * FF));
        acc.x += w.x * v0.x + w.y * v1.x + w.z * v2.x + w.w * v3.x;
        acc.y += w.x * v0.y + w.y * v1.y + w.z * v2.y + w.w * v3.y;
        acc.z += w.x * v0.z + w.y * v1.z + w.z * v2.z + w.w * v3.z;
        acc.w += w.x * v0.w + w.y * v1.w + w.z * v2.w + w.w * v3.w;
    }

    float scale = dir ? g_inv_in[n] : 1.0f;
    float4 r = make_float4(scale * acc.x, scale * acc.y, scale * acc.z, scale * acc.w);
    float* orow = g_basis + (size_t)flat * KC;
    if (dir == 0) {  // write-through term 0 = X
        float4 xv = __ldg(reinterpret_cast<const float4*>(x + (size_t)flat * FF + l * 4));
        *reinterpret_cast<float4*>(orow + l * 4) = xv;
    }
    *reinterpret_cast<float4*>(orow + tout * FF + l * 4) = r;
}

// ---------------- lean gather propagation (steps 2..4) ----------------
__global__ void __launch_bounds__(128) prop_pair_kernel(
    int tin_o, int tin_i, int tout_o, int tout_i, int tsub, float alpha)
{
    int tid = threadIdx.x;
    int g = tid >> 4, l = tid & 15;
    int flat = blockIdx.x * 8 + g;        // [0, MROWS)
    int bt = flat / NN, n = flat - bt * NN;
    int dir = blockIdx.y;

    const unsigned short* idx;
    const float* wq;
    int b0, b1, tin, tout;
    if (dir == 0) {
        idx = g_i16_dst; wq = g_wq_dst;
        b0 = g_pptr_dst[n]; b1 = g_pptr_dst[n + 1];
        tin = tin_o; tout = tout_o;
    } else {
        idx = g_i16_src; wq = g_wq_src;
        b0 = g_pptr_src[n]; b1 = g_pptr_src[n + 1];
        tin = tin_i; tout = tout_i;
    }

    const char* base = (const char*)(g_basis + (size_t)bt * NN * KC + tin * FF) + l * 16;
    float4 acc = make_float4(0.f, 0.f, 0.f, 0.f);

    for (int e = b0; e < b1; e += 4) {
        uint2 q = *reinterpret_cast<const uint2*>(idx + e);
        float4 w = *reinterpret_cast<const float4*>(wq + e);
        int i0 = q.x & 0xffff, i1 = q.x >> 16;
        int i2 = q.y & 0xffff, i3 = q.y >> 16;
        float4 v0 = __ldg(reinterpret_cast<const float4*>(base + (size_t)i0 * (KC * 4)));
        float4 v1 = __ldg(reinterpret_cast<const float4*>(base + (size_t)i1 * (KC * 4)));
        float4 v2 = __ldg(reinterpret_cast<const float4*>(base + (size_t)i2 * (KC * 4)));
        float4 v3 = __ldg(reinterpret_cast<const float4*>(base + (size_t)i3 * (KC * 4)));
        acc.x += w.x * v0.x + w.y * v1.x + w.z * v2.x + w.w * v3.x;
        acc.y += w.x * v0.y + w.y * v1.y + w.z * v2.y + w.w * v3.y;
        acc.z += w.x * v0.z + w.y * v1.z + w.z * v2.z + w.w * v3.z;
        acc.w += w.x * v0.w + w.y * v1.w + w.z * v2.w + w.w * v3.w;
    }

    float scale = dir ? alpha * g_inv_in[n] : alpha;
    float4 r = make_float4(scale * acc.x, scale * acc.y, scale * acc.z, scale * acc.w);
    float* orow = g_basis + (size_t)flat * KC;
    if (tsub >= 0) {
        float4 s4 = *reinterpret_cast<const float4*>(orow + tsub * FF + l * 4);
        r.x -= s4.x; r.y -= s4.y; r.z -= s4.z; r.w -= s4.w;
    }
    *reinterpret_cast<float4*>(orow + tout * FF + l * 4) = r;
}

// ---------------- fp16 tensor-core GEMM (192000x576 @ 576x128) + gate + LN ----------------
// mma.sync.m16n8k16.f16: 576 MMAs/warp (half of tf32 k8). A in smem as half2-pair
// uint2 with XOR swizzle (conflict-free LDS.64 reads); B pre-packed in g_Bpre, staged
// at stride 132 (conflict-free). Double-buffered, one sync per stage.
#define TM 128
#define BS2W 132
__global__ void __launch_bounds__(256, 2) gemm_tc_kernel(
    const float* __restrict__ bz, const float* __restrict__ bh,
    const float* __restrict__ lng, const float* __restrict__ lnb)
{
    __shared__ uint2 As2[2][TM * 4];      // [row][pair-slot], slot = p ^ (row&3)
    __shared__ uint2 Bs2[2][4 * BS2W];    // [p][col], row stride 132

    int tid = threadIdx.x;
    int w = tid >> 5, lane = tid & 31;
    int g = lane >> 2, tg = lane & 3;
    int block_row = blockIdx.x * TM;

    float acc[16][4];
#pragma unroll
    for (int j = 0; j < 16; j++)
#pragma unroll
        for (int i = 0; i < 4; i++) acc[j][i] = 0.f;

    bool aload = tid < 128;
    int lrow = tid & 127;                 // A: row; B: col n
    const float* aptr = &g_basis[(size_t)(block_row + lrow) * KC];
    const uint2* bpre = &g_Bpre[lrow * 4];

    // prologue prefetch (stage 0)
    float4 av0, av1, av2, av3;
    uint4 bv0, bv1;
    if (aload) {
        av0 = *reinterpret_cast<const float4*>(aptr);
        av1 = *reinterpret_cast<const float4*>(aptr + 4);
        av2 = *reinterpret_cast<const float4*>(aptr + 8);
        av3 = *reinterpret_cast<const float4*>(aptr + 12);
    } else {
        bv0 = *reinterpret_cast<const uint4*>(bpre);
        bv1 = *reinterpret_cast<const uint4*>(bpre + 2);
    }

#pragma unroll 1
    for (int t = 0; t < NSTAGE; t++) {
        int buf = t & 1;
        if (aload) {
            int sb = lrow * 4, sw = lrow & 3;
            As2[buf][sb + (0 ^ sw)] = make_uint2(pack2(av0.x, av0.y), pack2(av2.x, av2.y));
            As2[buf][sb + (1 ^ sw)] = make_uint2(pack2(av0.z, av0.w), pack2(av2.z, av2.w));
            As2[buf][sb + (2 ^ sw)] = make_uint2(pack2(av1.x, av1.y), pack2(av3.x, av3.y));
            As2[buf][sb + (3 ^ sw)] = make_uint2(pack2(av1.z, av1.w), pack2(av3.z, av3.w));
        } else {
            Bs2[buf][0 * BS2W + lrow] = make_uint2(bv0.x, bv0.y);
            Bs2[buf][1 * BS2W + lrow] = make_uint2(bv0.z, bv0.w);
            Bs2[buf][2 * BS2W + lrow] = make_uint2(bv1.x, bv1.y);
            Bs2[buf][3 * BS2W + lrow] = make_uint2(bv1.z, bv1.w);
        }
        __syncthreads();

        if (t + 1 < NSTAGE) {   // prefetch next stage while MMAs run
            int k1 = (t + 1) * 16;
            if (aload) {
                av0 = *reinterpret_cast<const float4*>(aptr + k1);
                av1 = *reinterpret_cast<const float4*>(aptr + k1 + 4);
                av2 = *reinterpret_cast<const float4*>(aptr + k1 + 8);
                av3 = *reinterpret_cast<const float4*>(aptr + k1 + 12);
            } else {
                const uint2* bp = bpre + (size_t)(t + 1) * 128 * 4;
                bv0 = *reinterpret_cast<const uint4*>(bp);
                bv1 = *reinterpret_cast<const uint4*>(bp + 2);
            }
        }

        const uint2* Ab = As2[buf];
        const uint2* Bb = Bs2[buf];
        int sw = g & 3;
        uint2 pa0 = Ab[(w * 16 + g) * 4 + (tg ^ sw)];       // rows g: (k,k+8) pairs
        uint2 pa1 = Ab[(w * 16 + g + 8) * 4 + (tg ^ sw)];   // rows g+8
#pragma unroll
        for (int j = 0; j < 16; j++) {
            uint2 pb = Bb[tg * BS2W + j * 8 + g];
            mma_f16(acc[j], pa0.x, pa1.x, pa0.y, pa1.y, pb.x, pb.y);
        }
        // single sync per stage: next iteration's pre-compute sync protects buffers
    }

    // ---- epilogue: gate + LayerNorm, register-resident (same C layout as k8) ----
#pragma unroll
    for (int rs = 0; rs < 2; rs++) {
        int row = block_row + w * 16 + g + rs * 8;
        float gv[8][2];
        float sum = 0.f, sq = 0.f;
#pragma unroll
        for (int j = 0; j < 8; j++) {
#pragma unroll
            for (int s = 0; s < 2; s++) {
                int col = j * 8 + tg * 2 + s;
                float vz = acc[j][rs * 2 + s] + __ldg(bz + col);
                float vh = acc[j + 8][rs * 2 + s] + __ldg(bh + col);
                float z = 1.f / (1.f + expf(-vz));
                float val = fmaxf(0.f, (1.f - z) * tanhf(vh));
                gv[j][s] = val;
                sum += val; sq += val * val;
            }
        }
        sum += __shfl_xor_sync(0xffffffffu, sum, 1);
        sq  += __shfl_xor_sync(0xffffffffu, sq, 1);
        sum += __shfl_xor_sync(0xffffffffu, sum, 2);
        sq  += __shfl_xor_sync(0xffffffffu, sq, 2);
        float mu = sum * (1.f / 64.f);
        float var = fmaxf(sq * (1.f / 64.f) - mu * mu, 0.f);
        float rstd = rsqrtf(var + LN_EPS);
        float* orow = g_hn + (size_t)row * FF;
#pragma unroll
        for (int j = 0; j < 8; j++) {
            int col = j * 8 + tg * 2;
            float2 o;
            o.x = (gv[j][0] - mu) * rstd * __ldg(lng + col)     + __ldg(lnb + col);
            o.y = (gv[j][1] - mu) * rstd * __ldg(lng + col + 1) + __ldg(lnb + col + 1);
            *reinterpret_cast<float2*>(orow + col) = o;
        }
    }
}

// ---------------- final linear head ----------------
__global__ void out_init_kernel(float* __restrict__ out, const float* __restrict__ lb) {
    int i = threadIdx.x;
    if (i < BB * CC) out[i] = lb[i % CC];
}

#define CH 1024
__global__ void __launch_bounds__(256) final_linear_kernel(
    const float* __restrict__ lin_w, float* __restrict__ out)
{
    __shared__ float ws[CC][CH];
    __shared__ float red[8][CC];
    int base = blockIdx.x * CH;   // 750 blocks * 1024 = 768000
    int tid = threadIdx.x;
    for (int i = tid; i < CC * CH; i += 256) {
        int c = i / CH, o = i % CH;
        ws[c][o] = lin_w[(size_t)c * LDIM + base + o];
    }
    __syncthreads();
    int w = tid >> 5, lane = tid & 31;
    for (int b = 0; b < BB; b++) {
        float a[CC];
#pragma unroll
        for (int c = 0; c < CC; c++) a[c] = 0.f;
        const float* hb = g_hn + (size_t)b * LDIM + base;
        for (int i = tid; i < CH; i += 256) {
            float hv = hb[i];
#pragma unroll
            for (int c = 0; c < CC; c++) a[c] += hv * ws[c][i];
        }
#pragma unroll
        for (int o = 16; o; o >>= 1)
#pragma unroll
            for (int c = 0; c < CC; c++) a[c] += __shfl_down_sync(0xffffffffu, a[c], o);
        if (lane == 0)
#pragma unroll
            for (int c = 0; c < CC; c++) red[w][c] = a[c];
        __syncthreads();
        if (tid < CC) {
            float s = 0.f;
#pragma unroll
            for (int ww = 0; ww < 8; ww++) s += red[ww][tid];
            atomicAdd(&out[b * CC + tid], s);
        }
        __syncthreads();
    }
}

// ---------------- launch ----------------
extern "C" void kernel_launch(void* const* d_in, const int* in_sizes, int n_in,
                              void* d_out, int out_size) {
    const float* x    = (const float*)d_in[0];
    const int*   ei   = (const int*)d_in[1];
    const float* Wz   = (const float*)d_in[2];
    const float* bz   = (const float*)d_in[3];
    // d_in[4], d_in[5] = W_r, b_r -> dead code (h0 == 0)
    const float* Wh   = (const float*)d_in[6];
    const float* bh   = (const float*)d_in[7];
    const float* lng  = (const float*)d_in[8];
    const float* lnb  = (const float*)d_in[9];
    const float* linw = (const float*)d_in[10];
    const float* linb = (const float*)d_in[11];
    float* out = (float*)d_out;

    setup_kernel<<<1, 1024>>>(ei, Wz, Wh);                           // launch 1

    dim3 pgrid(MROWS / 8, 2);
    // terms: 0=X, 1..4 = out-chain, 5..8 = in-chain (shared Tx0 history = out-chain terms)
    prop_first_kernel<<<pgrid, 128>>>(x);                            // launch 2 (terms 0,1,5)
    prop_pair_kernel<<<pgrid, 128>>>(1, 5, 2, 6, 0, 2.0f);           // launch 3
    prop_pair_kernel<<<pgrid, 128>>>(2, 6, 3, 7, 1, 2.0f);           // launch 4
    prop_pair_kernel<<<pgrid, 128>>>(3, 7, 4, 8, 2, 2.0f);           // launch 5

    gemm_tc_kernel<<<MROWS / TM, 256>>>(bz, bh, lng, lnb);           // launch 6

    out_init_kernel<<<1, 256>>>(out, linb);
    final_linear_kernel<<<LDIM / CH, 256>>>(linw, out);
}